// round 12
// baseline (speedup 1.0000x reference)
#include <cuda_runtime.h>

#define DIN  64
#define DOUT 64
#define HH   32
#define HP   16          // h-pairs
#define BB   2048
#define IQ   16          // Din split factor
#define IPQ  (DIN / IQ)  // 4 i's per CTA

// ---- device scratch ----
// w1p record per (o,i,hp): 64B = {0.5*w_f(h0),0.5*w_f(h1) f=0..6, 0.5*B1(h0),0.5*B1(h1)}
__device__ __align__(16) unsigned long long g_w1p[DOUT * DIN * HP * 8];   // 4 MB
// w2: per (o,i): 16 hp-pairs of W2 = 128B
__device__ __align__(16) unsigned long long g_w2[DOUT * DIN * HP];        // 1 MB
__device__ float g_xT[DIN * BB];
__device__ float g_sumB2[DOUT];

// ---- f32x2 helpers ----
__device__ __forceinline__ unsigned long long pack2(float a, float b) {
    unsigned long long v;
    asm("mov.b64 %0, {%1, %2};" : "=l"(v) : "f"(a), "f"(b));
    return v;
}
__device__ __forceinline__ void unpack2(unsigned long long v, float& a, float& b) {
    asm("mov.b64 {%0, %1}, %2;" : "=f"(a), "=f"(b) : "l"(v));
}
__device__ __forceinline__ unsigned long long fma2(unsigned long long a,
                                                   unsigned long long b,
                                                   unsigned long long c) {
    unsigned long long d;
    asm("fma.rn.f32x2 %0, %1, %2, %3;" : "=l"(d) : "l"(a), "l"(b), "l"(c));
    return d;
}
__device__ __forceinline__ float tanh_fast(float x) {
    float y;
    asm("tanh.approx.f32 %0, %1;" : "=f"(y) : "f"(x));
    return y;
}

// feats order matches reference: [x, sin(1x), sin(2x), sin(4x), cos(1x), cos(2x), cos(4x)]
__device__ __forceinline__ void make_feats(float x, unsigned long long* fp) {
    float s1 = __sinf(x),  c1 = __cosf(x);
    float x2 = x + x;
    float s2 = __sinf(x2), c2 = __cosf(x2);
    float x4 = x2 + x2;
    float s4 = __sinf(x4), c4 = __cosf(x4);
    fp[0] = pack2(x,  x);
    fp[1] = pack2(s1, s1);
    fp[2] = pack2(s2, s2);
    fp[3] = pack2(s4, s4);
    fp[4] = pack2(c1, c1);
    fp[5] = pack2(c2, c2);
    fp[6] = pack2(c4, c4);
}

// one edge-MLP evaluation for one b (h-pair packed), weights pre-scaled by 0.5
__device__ __forceinline__ void edge_eval(ulonglong2 q0, ulonglong2 q1,
                                          ulonglong2 q2, ulonglong2 q3,
                                          unsigned long long w2p,
                                          const unsigned long long* f,
                                          unsigned long long& acc) {
    unsigned long long u = fma2(q0.x, f[0], q3.y);  // q3.y = 0.5*B1 pair
    u = fma2(q0.y, f[1], u);
    u = fma2(q1.x, f[2], u);
    u = fma2(q1.y, f[3], u);
    u = fma2(q2.x, f[4], u);
    u = fma2(q2.y, f[5], u);
    u = fma2(q3.x, f[6], u);                        // u = h/2
    float a0, a1;
    unpack2(u, a0, a1);
    unsigned long long tp = pack2(tanh_fast(a0), tanh_fast(a1));
    unsigned long long s = fma2(u, tp, u);          // silu(h) = (h/2)(1+tanh(h/2))
    acc = fma2(s, w2p, acc);
}

// ---- prologue 1: tiled x transpose (coalesced both sides) ----
__global__ void prep_x_t(const float* __restrict__ x) {
    __shared__ float tile[32][33];
    int bx = blockIdx.x;             // 64 b-tiles of 32
    int by = blockIdx.y;             // 2 i-tiles of 32
    int tx = threadIdx.x, ty = threadIdx.y;   // 32 x 8
#pragma unroll
    for (int k = 0; k < 4; k++) {
        int b = bx * 32 + ty + k * 8;
        tile[ty + k * 8][tx] = x[b * DIN + by * 32 + tx];
    }
    __syncthreads();
#pragma unroll
    for (int k = 0; k < 4; k++) {
        int i = by * 32 + ty + k * 8;
        g_xT[i * BB + bx * 32 + tx] = tile[tx][ty + k * 8];
    }
}

// ---- prologue 2: weight repack + B2 row-sum ----
#define NRP (DOUT * DIN * HP)
__global__ void prep_w(const float* __restrict__ W1, const float* __restrict__ W2,
                       const float* __restrict__ B1, const float* __restrict__ B2) {
    int t = blockIdx.x * 256 + threadIdx.x;
    if (t < NRP) {
        int hp = t & 15;
        int i  = (t >> 4) & 63;
        int o  = t >> 10;
        int h0 = hp * 2, h1 = h0 + 1;

        const float* w1b = W1 + (((size_t)i * DOUT + o) * HH) * 7;  // W1[i][o][h][f]
        float* dst = ((float*)g_w1p) + (size_t)t * 16;
#pragma unroll
        for (int f = 0; f < 7; f++) {
            dst[2 * f]     = 0.5f * w1b[h0 * 7 + f];
            dst[2 * f + 1] = 0.5f * w1b[h1 * 7 + f];
        }
        const float* b1b = B1 + ((size_t)i * DOUT + o) * HH;
        dst[14] = 0.5f * b1b[h0];
        dst[15] = 0.5f * b1b[h1];

        const float* w2b = W2 + ((size_t)i * DOUT + o) * HH;  // W2[i][o][0][h]
        float* d2 = ((float*)g_w2) + (((size_t)o * DIN + i) * HP + hp) * 2;
        d2[0] = w2b[h0];
        d2[1] = w2b[h1];
        return;
    }
    t -= NRP;
    if (t < DOUT) {
        float s = 0.f;
        for (int i = 0; i < DIN; i++) s += B2[i * DOUT + t];
        g_sumB2[t] = s;
    }
}

// ---- prologue 3: initialize out with bias row-sums (atomic accumulation base) ----
__global__ void out_init(float* __restrict__ out) {
    int t = blockIdx.x * 256 + threadIdx.x;      // t = b*DOUT + o
    if (t < BB * DOUT) out[t] = g_sumB2[t & 63];
}

// ---- main fused kernel (launch #4 -> profiled) ----
// CTA = 8 warps, one (o, iq, bh): 4 i's, 1024 b's. 4.5KB weight slice in smem.
// Lane owns 4 b's -> each weight LDS serves 40 FFMA2 (L1 traffic halved vs 2b).
// 2 CTAs/SM (regs ~105). grid = 64 o * 16 iq * 2 bh = 2048 CTAs.
__global__ void __launch_bounds__(256, 2) kan_main(float* __restrict__ out) {
    __shared__ __align__(16) ulonglong2 s_w1[IPQ * HP * 4];   // 256 entries, 4 KB
    __shared__ __align__(16) ulonglong2 s_w2[IPQ * HP / 2];   // 32 entries, 0.5 KB

    int lane = threadIdx.x & 31;
    int w    = threadIdx.x >> 5;
    int o    = blockIdx.x & 63;
    int iq   = (blockIdx.x >> 6) & 15;
    int bh   = blockIdx.x >> 10;            // 0..1
    int b0   = bh * 1024 + w * 128 + lane;
    int i0   = iq * IPQ;

    // cooperative weight-slice load (coalesced LDG.128 -> STS.128)
    {
        const ulonglong2* gw1 = ((const ulonglong2*)g_w1p) + ((size_t)o * DIN + i0) * (HP * 4);
        const ulonglong2* gw2 = ((const ulonglong2*)g_w2)  + ((size_t)o * DIN + i0) * (HP / 2);
        s_w1[threadIdx.x] = gw1[threadIdx.x];                      // 256 entries
        if (threadIdx.x < IPQ * HP / 2) s_w2[threadIdx.x] = gw2[threadIdx.x];
    }
    __syncthreads();

    unsigned long long accA = 0ull, accB = 0ull, accC = 0ull, accD = 0ull;
    unsigned long long fA[7], fB[7], fC[7], fD[7];

    const float* xr = g_xT + i0 * BB + b0;
    float nxa = xr[0], nxb = xr[32], nxc = xr[64], nxd = xr[96];

#pragma unroll 1
    for (int ii = 0; ii < IPQ; ii++) {
        float xa = nxa, xb = nxb, xc = nxc, xd = nxd;
        if (ii + 1 < IPQ) {                      // prefetch next i's x
            const float* xn = xr + (ii + 1) * BB;
            nxa = xn[0]; nxb = xn[32]; nxc = xn[64]; nxd = xn[96];
        }
        make_feats(xa, fA);
        make_feats(xb, fB);
        make_feats(xc, fC);
        make_feats(xd, fD);

        const ulonglong2* wr  = s_w1 + ii * (HP * 4);
        const ulonglong2* w2r = s_w2 + ii * (HP / 2);

#pragma unroll 1
        for (int hpp = 0; hpp < HP / 2; hpp++) {
            ulonglong2 w2q = w2r[hpp];      // W2 pairs for hp=2hpp (.x), 2hpp+1 (.y)
#pragma unroll
            for (int k = 0; k < 2; k++) {
                int hp = 2 * hpp + k;
                ulonglong2 q0 = wr[hp * 4 + 0];
                ulonglong2 q1 = wr[hp * 4 + 1];
                ulonglong2 q2 = wr[hp * 4 + 2];
                ulonglong2 q3 = wr[hp * 4 + 3];
                unsigned long long w2p = k ? w2q.y : w2q.x;
                edge_eval(q0, q1, q2, q3, w2p, fA, accA);
                edge_eval(q0, q1, q2, q3, w2p, fB, accB);
                edge_eval(q0, q1, q2, q3, w2p, fC, accC);
                edge_eval(q0, q1, q2, q3, w2p, fD, accD);
            }
        }
    }

    float r0, r1;
    unpack2(accA, r0, r1); atomicAdd(&out[(size_t)(b0      ) * DOUT + o], r0 + r1);
    unpack2(accB, r0, r1); atomicAdd(&out[(size_t)(b0 + 32 ) * DOUT + o], r0 + r1);
    unpack2(accC, r0, r1); atomicAdd(&out[(size_t)(b0 + 64 ) * DOUT + o], r0 + r1);
    unpack2(accD, r0, r1); atomicAdd(&out[(size_t)(b0 + 96 ) * DOUT + o], r0 + r1);
}

extern "C" void kernel_launch(void* const* d_in, const int* in_sizes, int n_in,
                              void* d_out, int out_size) {
    const float* x  = (const float*)d_in[0];
    const float* W1 = (const float*)d_in[1];
    const float* W2 = (const float*)d_in[2];
    const float* B1 = (const float*)d_in[3];
    const float* B2 = (const float*)d_in[4];
    (void)in_sizes; (void)n_in; (void)out_size;

    dim3 tb(32, 8);
    dim3 tg(64, 2);
    prep_x_t<<<tg, tb>>>(x);                                    // launch 1
    prep_w<<<(NRP + DOUT + 255) / 256, 256>>>(W1, W2, B1, B2);  // launch 2
    out_init<<<(BB * DOUT + 255) / 256, 256>>>((float*)d_out);  // launch 3
    kan_main<<<2048, 256>>>((float*)d_out);                     // launch 4 (profiled)
}

// round 13
// speedup vs baseline: 1.1011x; 1.1011x over previous
#include <cuda_runtime.h>

#define DIN  64
#define DOUT 64
#define HH   32
#define HP   16          // h-pairs
#define BB   2048
#define IQ   8           // Din split factor
#define IPQ  (DIN / IQ)  // 8 i's per CTA

// ---- device scratch ----
// w1p record per (o,i,hp): 64B = {0.5*w_f(h0),0.5*w_f(h1) f=0..6, 0.5*B1(h0),0.5*B1(h1)}
__device__ __align__(16) unsigned long long g_w1p[DOUT * DIN * HP * 8];   // 4 MB
// w2: per (o,i): 16 hp-pairs of W2 = 128B
__device__ __align__(16) unsigned long long g_w2[DOUT * DIN * HP];        // 1 MB
__device__ float g_xT[DIN * BB];
__device__ float g_sumB2[DOUT];

// ---- f32x2 helpers ----
__device__ __forceinline__ unsigned long long pack2(float a, float b) {
    unsigned long long v;
    asm("mov.b64 %0, {%1, %2};" : "=l"(v) : "f"(a), "f"(b));
    return v;
}
__device__ __forceinline__ void unpack2(unsigned long long v, float& a, float& b) {
    asm("mov.b64 {%0, %1}, %2;" : "=f"(a), "=f"(b) : "l"(v));
}
__device__ __forceinline__ unsigned long long fma2(unsigned long long a,
                                                   unsigned long long b,
                                                   unsigned long long c) {
    unsigned long long d;
    asm("fma.rn.f32x2 %0, %1, %2, %3;" : "=l"(d) : "l"(a), "l"(b), "l"(c));
    return d;
}
__device__ __forceinline__ float tanh_fast(float x) {
    float y;
    asm("tanh.approx.f32 %0, %1;" : "=f"(y) : "f"(x));
    return y;
}

// feats order matches reference: [x, sin(1x), sin(2x), sin(4x), cos(1x), cos(2x), cos(4x)]
__device__ __forceinline__ void make_feats(float x, unsigned long long* fp) {
    float s1 = __sinf(x),  c1 = __cosf(x);
    float x2 = x + x;
    float s2 = __sinf(x2), c2 = __cosf(x2);
    float x4 = x2 + x2;
    float s4 = __sinf(x4), c4 = __cosf(x4);
    fp[0] = pack2(x,  x);
    fp[1] = pack2(s1, s1);
    fp[2] = pack2(s2, s2);
    fp[3] = pack2(s4, s4);
    fp[4] = pack2(c1, c1);
    fp[5] = pack2(c2, c2);
    fp[6] = pack2(c4, c4);
}

// one edge-MLP evaluation for one b (h-pair packed), weights pre-scaled by 0.5
__device__ __forceinline__ void edge_eval(ulonglong2 q0, ulonglong2 q1,
                                          ulonglong2 q2, ulonglong2 q3,
                                          unsigned long long w2p,
                                          const unsigned long long* f,
                                          unsigned long long& acc) {
    unsigned long long u = fma2(q0.x, f[0], q3.y);  // q3.y = 0.5*B1 pair
    u = fma2(q0.y, f[1], u);
    u = fma2(q1.x, f[2], u);
    u = fma2(q1.y, f[3], u);
    u = fma2(q2.x, f[4], u);
    u = fma2(q2.y, f[5], u);
    u = fma2(q3.x, f[6], u);                        // u = h/2
    float a0, a1;
    unpack2(u, a0, a1);
    unsigned long long tp = pack2(tanh_fast(a0), tanh_fast(a1));
    unsigned long long s = fma2(u, tp, u);          // silu(h) = (h/2)(1+tanh(h/2))
    acc = fma2(s, w2p, acc);
}

// ---- prologue 1: tiled x transpose (coalesced both sides) ----
__global__ void prep_x_t(const float* __restrict__ x) {
    __shared__ float tile[32][33];
    int bx = blockIdx.x;             // 64 b-tiles of 32
    int by = blockIdx.y;             // 2 i-tiles of 32
    int tx = threadIdx.x, ty = threadIdx.y;   // 32 x 8
#pragma unroll
    for (int k = 0; k < 4; k++) {
        int b = bx * 32 + ty + k * 8;
        tile[ty + k * 8][tx] = x[b * DIN + by * 32 + tx];
    }
    __syncthreads();
#pragma unroll
    for (int k = 0; k < 4; k++) {
        int i = by * 32 + ty + k * 8;
        g_xT[i * BB + bx * 32 + tx] = tile[tx][ty + k * 8];
    }
}

// ---- prologue 2: weight repack + B2 row-sum ----
#define NRP (DOUT * DIN * HP)
__global__ void prep_w(const float* __restrict__ W1, const float* __restrict__ W2,
                       const float* __restrict__ B1, const float* __restrict__ B2) {
    int t = blockIdx.x * 256 + threadIdx.x;
    if (t < NRP) {
        int hp = t & 15;
        int i  = (t >> 4) & 63;
        int o  = t >> 10;
        int h0 = hp * 2, h1 = h0 + 1;

        const float* w1b = W1 + (((size_t)i * DOUT + o) * HH) * 7;  // W1[i][o][h][f]
        float* dst = ((float*)g_w1p) + (size_t)t * 16;
#pragma unroll
        for (int f = 0; f < 7; f++) {
            dst[2 * f]     = 0.5f * w1b[h0 * 7 + f];
            dst[2 * f + 1] = 0.5f * w1b[h1 * 7 + f];
        }
        const float* b1b = B1 + ((size_t)i * DOUT + o) * HH;
        dst[14] = 0.5f * b1b[h0];
        dst[15] = 0.5f * b1b[h1];

        const float* w2b = W2 + ((size_t)i * DOUT + o) * HH;  // W2[i][o][0][h]
        float* d2 = ((float*)g_w2) + (((size_t)o * DIN + i) * HP + hp) * 2;
        d2[0] = w2b[h0];
        d2[1] = w2b[h1];
        return;
    }
    t -= NRP;
    if (t < DOUT) {
        float s = 0.f;
        for (int i = 0; i < DIN; i++) s += B2[i * DOUT + t];
        g_sumB2[t] = s;
    }
}

// ---- prologue 3: initialize out with bias row-sums (atomic accumulation base) ----
__global__ void out_init(float* __restrict__ out) {
    int t = blockIdx.x * 256 + threadIdx.x;      // t = b*DOUT + o
    if (t < BB * DOUT) out[t] = g_sumB2[t & 63];
}

// ---- main fused kernel (launch #4 -> profiled) ----
// CTA = 4 warps (128 thr), one (o, iq, bo): 8 i's, 256 b's. 9KB weight slice in smem.
// Lane owns 2 b's (the proven R11 inner body). __launch_bounds__(128,8) caps regs
// at 64 -> 8 CTAs/SM = 32 warps/SM (vs 24): more warps to overlap the three
// co-equal walls (FMA ~62us, LDS ~66us, MUFU ~67us).
// grid = 64 o * 8 iq * 8 bo = 4096 CTAs.
__global__ void __launch_bounds__(128, 8) kan_main(float* __restrict__ out) {
    __shared__ __align__(16) ulonglong2 s_w1[IPQ * HP * 4];   // 512 entries, 8 KB
    __shared__ __align__(16) ulonglong2 s_w2[IPQ * HP / 2];   // 64 entries, 1 KB

    int lane = threadIdx.x & 31;
    int w    = threadIdx.x >> 5;
    int o    = blockIdx.x & 63;
    int iq   = (blockIdx.x >> 6) & 7;
    int bo   = blockIdx.x >> 9;             // 0..7
    int b0   = bo * 256 + w * 64 + lane;
    int i0   = iq * IPQ;

    // cooperative weight-slice load (coalesced LDG.128 -> STS.128)
    {
        const ulonglong2* gw1 = ((const ulonglong2*)g_w1p) + ((size_t)o * DIN + i0) * (HP * 4);
        const ulonglong2* gw2 = ((const ulonglong2*)g_w2)  + ((size_t)o * DIN + i0) * (HP / 2);
#pragma unroll
        for (int t = threadIdx.x; t < IPQ * HP * 4; t += 128) s_w1[t] = gw1[t];
        if (threadIdx.x < IPQ * HP / 2) s_w2[threadIdx.x] = gw2[threadIdx.x];
    }
    __syncthreads();

    unsigned long long accA = 0ull, accB = 0ull;
    unsigned long long fA[7], fB[7];

    const float* xr = g_xT + i0 * BB + b0;
    float nxa = xr[0], nxb = xr[32];

#pragma unroll 1
    for (int ii = 0; ii < IPQ; ii++) {
        float xa = nxa, xb = nxb;
        if (ii + 1 < IPQ) {                      // prefetch next i's x
            nxa = xr[(ii + 1) * BB];
            nxb = xr[(ii + 1) * BB + 32];
        }
        make_feats(xa, fA);
        make_feats(xb, fB);

        const ulonglong2* wr  = s_w1 + ii * (HP * 4);
        const ulonglong2* w2r = s_w2 + ii * (HP / 2);

#pragma unroll 2
        for (int hpp = 0; hpp < HP / 2; hpp++) {
            ulonglong2 w2q = w2r[hpp];      // W2 pairs for hp=2hpp (.x), 2hpp+1 (.y)
#pragma unroll
            for (int k = 0; k < 2; k++) {
                int hp = 2 * hpp + k;
                ulonglong2 q0 = wr[hp * 4 + 0];
                ulonglong2 q1 = wr[hp * 4 + 1];
                ulonglong2 q2 = wr[hp * 4 + 2];
                ulonglong2 q3 = wr[hp * 4 + 3];
                unsigned long long w2p = k ? w2q.y : w2q.x;
                edge_eval(q0, q1, q2, q3, w2p, fA, accA);
                edge_eval(q0, q1, q2, q3, w2p, fB, accB);
            }
        }
    }

    float r0, r1;
    unpack2(accA, r0, r1);
    atomicAdd(&out[(size_t)b0 * DOUT + o], r0 + r1);          // RED.ADD.F32
    unpack2(accB, r0, r1);
    atomicAdd(&out[(size_t)(b0 + 32) * DOUT + o], r0 + r1);
}

extern "C" void kernel_launch(void* const* d_in, const int* in_sizes, int n_in,
                              void* d_out, int out_size) {
    const float* x  = (const float*)d_in[0];
    const float* W1 = (const float*)d_in[1];
    const float* W2 = (const float*)d_in[2];
    const float* B1 = (const float*)d_in[3];
    const float* B2 = (const float*)d_in[4];
    (void)in_sizes; (void)n_in; (void)out_size;

    dim3 tb(32, 8);
    dim3 tg(64, 2);
    prep_x_t<<<tg, tb>>>(x);                                    // launch 1
    prep_w<<<(NRP + DOUT + 255) / 256, 256>>>(W1, W2, B1, B2);  // launch 2
    out_init<<<(BB * DOUT + 255) / 256, 256>>>((float*)d_out);  // launch 3
    kan_main<<<4096, 128>>>((float*)d_out);                     // launch 4 (profiled)
}

// round 14
// speedup vs baseline: 1.1274x; 1.0239x over previous
#include <cuda_runtime.h>

#define DIN  64
#define DOUT 64
#define HH   32
#define HP   16          // h-pairs
#define BB   2048
#define IQ   16          // Din split factor
#define IPQ  (DIN / IQ)  // 4 i's per CTA

// ---- device scratch ----
// w1p record per (o,i,hp): 64B = {0.5*w_f(h0),0.5*w_f(h1) f=0..6, 0.5*B1(h0),0.5*B1(h1)}
__device__ __align__(16) unsigned long long g_w1p[DOUT * DIN * HP * 8];   // 4 MB
// w2: per (o,i): 16 hp-pairs of W2 = 128B
__device__ __align__(16) unsigned long long g_w2[DOUT * DIN * HP];        // 1 MB
__device__ float g_xT[DIN * BB];
__device__ float g_sumB2[DOUT];

// ---- f32x2 helpers ----
__device__ __forceinline__ unsigned long long pack2(float a, float b) {
    unsigned long long v;
    asm("mov.b64 %0, {%1, %2};" : "=l"(v) : "f"(a), "f"(b));
    return v;
}
__device__ __forceinline__ void unpack2(unsigned long long v, float& a, float& b) {
    asm("mov.b64 {%0, %1}, %2;" : "=f"(a), "=f"(b) : "l"(v));
}
__device__ __forceinline__ unsigned long long fma2(unsigned long long a,
                                                   unsigned long long b,
                                                   unsigned long long c) {
    unsigned long long d;
    asm("fma.rn.f32x2 %0, %1, %2, %3;" : "=l"(d) : "l"(a), "l"(b), "l"(c));
    return d;
}
__device__ __forceinline__ float tanh_fast(float x) {
    float y;
    asm("tanh.approx.f32 %0, %1;" : "=f"(y) : "f"(x));
    return y;
}

// feats order matches reference: [x, sin(1x), sin(2x), sin(4x), cos(1x), cos(2x), cos(4x)]
__device__ __forceinline__ void make_feats(float x, unsigned long long* fp) {
    float s1 = __sinf(x),  c1 = __cosf(x);
    float x2 = x + x;
    float s2 = __sinf(x2), c2 = __cosf(x2);
    float x4 = x2 + x2;
    float s4 = __sinf(x4), c4 = __cosf(x4);
    fp[0] = pack2(x,  x);
    fp[1] = pack2(s1, s1);
    fp[2] = pack2(s2, s2);
    fp[3] = pack2(s4, s4);
    fp[4] = pack2(c1, c1);
    fp[5] = pack2(c2, c2);
    fp[6] = pack2(c4, c4);
}

// one edge-MLP evaluation for one b (h-pair packed), weights pre-scaled by 0.5
__device__ __forceinline__ void edge_eval(ulonglong2 q0, ulonglong2 q1,
                                          ulonglong2 q2, ulonglong2 q3,
                                          unsigned long long w2p,
                                          const unsigned long long* f,
                                          unsigned long long& acc) {
    unsigned long long u = fma2(q0.x, f[0], q3.y);  // q3.y = 0.5*B1 pair
    u = fma2(q0.y, f[1], u);
    u = fma2(q1.x, f[2], u);
    u = fma2(q1.y, f[3], u);
    u = fma2(q2.x, f[4], u);
    u = fma2(q2.y, f[5], u);
    u = fma2(q3.x, f[6], u);                        // u = h/2
    float a0, a1;
    unpack2(u, a0, a1);
    unsigned long long tp = pack2(tanh_fast(a0), tanh_fast(a1));
    unsigned long long s = fma2(u, tp, u);          // silu(h) = (h/2)(1+tanh(h/2))
    acc = fma2(s, w2p, acc);
}

// ---- prologue 1: tiled x transpose (coalesced both sides) ----
__global__ void prep_x_t(const float* __restrict__ x) {
    __shared__ float tile[32][33];
    int bx = blockIdx.x;             // 64 b-tiles of 32
    int by = blockIdx.y;             // 2 i-tiles of 32
    int tx = threadIdx.x, ty = threadIdx.y;   // 32 x 8
#pragma unroll
    for (int k = 0; k < 4; k++) {
        int b = bx * 32 + ty + k * 8;
        tile[ty + k * 8][tx] = x[b * DIN + by * 32 + tx];
    }
    __syncthreads();
#pragma unroll
    for (int k = 0; k < 4; k++) {
        int i = by * 32 + ty + k * 8;
        g_xT[i * BB + bx * 32 + tx] = tile[tx][ty + k * 8];
    }
}

// ---- prologue 2: weight repack + B2 row-sum ----
#define NRP (DOUT * DIN * HP)
__global__ void prep_w(const float* __restrict__ W1, const float* __restrict__ W2,
                       const float* __restrict__ B1, const float* __restrict__ B2) {
    int t = blockIdx.x * 256 + threadIdx.x;
    if (t < NRP) {
        int hp = t & 15;
        int i  = (t >> 4) & 63;
        int o  = t >> 10;
        int h0 = hp * 2, h1 = h0 + 1;

        const float* w1b = W1 + (((size_t)i * DOUT + o) * HH) * 7;  // W1[i][o][h][f]
        float* dst = ((float*)g_w1p) + (size_t)t * 16;
#pragma unroll
        for (int f = 0; f < 7; f++) {
            dst[2 * f]     = 0.5f * w1b[h0 * 7 + f];
            dst[2 * f + 1] = 0.5f * w1b[h1 * 7 + f];
        }
        const float* b1b = B1 + ((size_t)i * DOUT + o) * HH;
        dst[14] = 0.5f * b1b[h0];
        dst[15] = 0.5f * b1b[h1];

        const float* w2b = W2 + ((size_t)i * DOUT + o) * HH;  // W2[i][o][0][h]
        float* d2 = ((float*)g_w2) + (((size_t)o * DIN + i) * HP + hp) * 2;
        d2[0] = w2b[h0];
        d2[1] = w2b[h1];
        return;
    }
    t -= NRP;
    if (t < DOUT) {
        float s = 0.f;
        for (int i = 0; i < DIN; i++) s += B2[i * DOUT + t];
        g_sumB2[t] = s;
    }
}

// ---- prologue 3: initialize out with bias row-sums (atomic accumulation base) ----
__global__ void out_init(float* __restrict__ out) {
    int t = blockIdx.x * 256 + threadIdx.x;      // t = b*DOUT + o
    if (t < BB * DOUT) out[t] = g_sumB2[t & 63];
}

// ---- main fused kernel (launch #4 -> profiled) ----
// CTA = 4 warps (128 thr), one (o, iq, bo): 4 i's, 512 b's. 4.5KB slice in smem.
// Lane owns 4 b's -> LDS per unit work halves vs R13 (L1 wall 68% -> ~35%).
// __launch_bounds__(128,5): reg cap 102 (R12's 4b body wanted 94 -> no spills),
// 20 warps/SM = 5/SMSP, each warp 4 independent chains. hpp unroll 2 for load batching.
// grid = 64 o * 16 iq * 4 bo = 4096 CTAs (5.5 waves over 740 slots).
__global__ void __launch_bounds__(128, 5) kan_main(float* __restrict__ out) {
    __shared__ __align__(16) ulonglong2 s_w1[IPQ * HP * 4];   // 256 entries, 4 KB
    __shared__ __align__(16) ulonglong2 s_w2[IPQ * HP / 2];   // 32 entries, 0.5 KB

    int lane = threadIdx.x & 31;
    int w    = threadIdx.x >> 5;
    int o    = blockIdx.x & 63;
    int iq   = (blockIdx.x >> 6) & 15;
    int bo   = blockIdx.x >> 10;            // 0..3
    int b0   = bo * 512 + w * 128 + lane;
    int i0   = iq * IPQ;

    // cooperative weight-slice load (coalesced LDG.128 -> STS.128)
    {
        const ulonglong2* gw1 = ((const ulonglong2*)g_w1p) + ((size_t)o * DIN + i0) * (HP * 4);
        const ulonglong2* gw2 = ((const ulonglong2*)g_w2)  + ((size_t)o * DIN + i0) * (HP / 2);
#pragma unroll
        for (int t = threadIdx.x; t < IPQ * HP * 4; t += 128) s_w1[t] = gw1[t];
        if (threadIdx.x < IPQ * HP / 2) s_w2[threadIdx.x] = gw2[threadIdx.x];
    }
    __syncthreads();

    unsigned long long accA = 0ull, accB = 0ull, accC = 0ull, accD = 0ull;
    unsigned long long fA[7], fB[7], fC[7], fD[7];

    const float* xr = g_xT + i0 * BB + b0;
    float nxa = xr[0], nxb = xr[32], nxc = xr[64], nxd = xr[96];

#pragma unroll 1
    for (int ii = 0; ii < IPQ; ii++) {
        float xa = nxa, xb = nxb, xc = nxc, xd = nxd;
        if (ii + 1 < IPQ) {                      // prefetch next i's x
            const float* xn = xr + (ii + 1) * BB;
            nxa = xn[0]; nxb = xn[32]; nxc = xn[64]; nxd = xn[96];
        }
        make_feats(xa, fA);
        make_feats(xb, fB);
        make_feats(xc, fC);
        make_feats(xd, fD);

        const ulonglong2* wr  = s_w1 + ii * (HP * 4);
        const ulonglong2* w2r = s_w2 + ii * (HP / 2);

#pragma unroll 2
        for (int hpp = 0; hpp < HP / 2; hpp++) {
            ulonglong2 w2q = w2r[hpp];      // W2 pairs for hp=2hpp (.x), 2hpp+1 (.y)
#pragma unroll
            for (int k = 0; k < 2; k++) {
                int hp = 2 * hpp + k;
                ulonglong2 q0 = wr[hp * 4 + 0];
                ulonglong2 q1 = wr[hp * 4 + 1];
                ulonglong2 q2 = wr[hp * 4 + 2];
                ulonglong2 q3 = wr[hp * 4 + 3];
                unsigned long long w2p = k ? w2q.y : w2q.x;
                edge_eval(q0, q1, q2, q3, w2p, fA, accA);
                edge_eval(q0, q1, q2, q3, w2p, fB, accB);
                edge_eval(q0, q1, q2, q3, w2p, fC, accC);
                edge_eval(q0, q1, q2, q3, w2p, fD, accD);
            }
        }
    }

    float r0, r1;
    unpack2(accA, r0, r1); atomicAdd(&out[(size_t)(b0      ) * DOUT + o], r0 + r1);
    unpack2(accB, r0, r1); atomicAdd(&out[(size_t)(b0 + 32 ) * DOUT + o], r0 + r1);
    unpack2(accC, r0, r1); atomicAdd(&out[(size_t)(b0 + 64 ) * DOUT + o], r0 + r1);
    unpack2(accD, r0, r1); atomicAdd(&out[(size_t)(b0 + 96 ) * DOUT + o], r0 + r1);
}

extern "C" void kernel_launch(void* const* d_in, const int* in_sizes, int n_in,
                              void* d_out, int out_size) {
    const float* x  = (const float*)d_in[0];
    const float* W1 = (const float*)d_in[1];
    const float* W2 = (const float*)d_in[2];
    const float* B1 = (const float*)d_in[3];
    const float* B2 = (const float*)d_in[4];
    (void)in_sizes; (void)n_in; (void)out_size;

    dim3 tb(32, 8);
    dim3 tg(64, 2);
    prep_x_t<<<tg, tb>>>(x);                                    // launch 1
    prep_w<<<(NRP + DOUT + 255) / 256, 256>>>(W1, W2, B1, B2);  // launch 2
    out_init<<<(BB * DOUT + 255) / 256, 256>>>((float*)d_out);  // launch 3
    kan_main<<<4096, 128>>>((float*)d_out);                     // launch 4 (profiled)
}

// round 15
// speedup vs baseline: 1.1435x; 1.0142x over previous
#include <cuda_runtime.h>

#define DIN  64
#define DOUT 64
#define HH   32
#define HP   16          // h-pairs
#define BB   2048
#define IQ   16          // Din split factor
#define IPQ  (DIN / IQ)  // 4 i's per CTA

// ---- device scratch ----
// w1p record per (o,i,hp): 64B = {0.5*w_f(h0),0.5*w_f(h1) f=0..6, 0.5*B1(h0),0.5*B1(h1)}
__device__ __align__(16) unsigned long long g_w1p[DOUT * DIN * HP * 8];   // 4 MB
// w2: per (o,i): 16 hp-pairs of W2 = 128B
__device__ __align__(16) unsigned long long g_w2[DOUT * DIN * HP];        // 1 MB
__device__ float g_xT[DIN * BB];
__device__ float g_sumB2[DOUT];

// ---- f32x2 helpers ----
__device__ __forceinline__ unsigned long long pack2(float a, float b) {
    unsigned long long v;
    asm("mov.b64 %0, {%1, %2};" : "=l"(v) : "f"(a), "f"(b));
    return v;
}
__device__ __forceinline__ void unpack2(unsigned long long v, float& a, float& b) {
    asm("mov.b64 {%0, %1}, %2;" : "=f"(a), "=f"(b) : "l"(v));
}
__device__ __forceinline__ unsigned long long fma2(unsigned long long a,
                                                   unsigned long long b,
                                                   unsigned long long c) {
    unsigned long long d;
    asm("fma.rn.f32x2 %0, %1, %2, %3;" : "=l"(d) : "l"(a), "l"(b), "l"(c));
    return d;
}
__device__ __forceinline__ float tanh_fast(float x) {
    float y;
    asm("tanh.approx.f32 %0, %1;" : "=f"(y) : "f"(x));
    return y;
}

// feats order matches reference: [x, sin(1x), sin(2x), sin(4x), cos(1x), cos(2x), cos(4x)]
// 2x/4x via double-angle on the FMA pipe: MUFU only for sin(x), cos(x) (+tanh later).
__device__ __forceinline__ void make_feats(float x, unsigned long long* fp) {
    float s1 = __sinf(x), c1 = __cosf(x);
    float t1 = s1 + s1;
    float s2 = t1 * c1;
    float c2 = fmaf(-t1, s1, 1.f);
    float t2 = s2 + s2;
    float s4 = t2 * c2;
    float c4 = fmaf(-t2, s2, 1.f);
    fp[0] = pack2(x,  x);
    fp[1] = pack2(s1, s1);
    fp[2] = pack2(s2, s2);
    fp[3] = pack2(s4, s4);
    fp[4] = pack2(c1, c1);
    fp[5] = pack2(c2, c2);
    fp[6] = pack2(c4, c4);
}

// one edge-MLP evaluation for one b (h-pair packed), weights pre-scaled by 0.5
__device__ __forceinline__ void edge_eval(ulonglong2 q0, ulonglong2 q1,
                                          ulonglong2 q2, ulonglong2 q3,
                                          unsigned long long w2p,
                                          const unsigned long long* f,
                                          unsigned long long& acc) {
    unsigned long long u = fma2(q0.x, f[0], q3.y);  // q3.y = 0.5*B1 pair
    u = fma2(q0.y, f[1], u);
    u = fma2(q1.x, f[2], u);
    u = fma2(q1.y, f[3], u);
    u = fma2(q2.x, f[4], u);
    u = fma2(q2.y, f[5], u);
    u = fma2(q3.x, f[6], u);                        // u = h/2
    float a0, a1;
    unpack2(u, a0, a1);
    unsigned long long tp = pack2(tanh_fast(a0), tanh_fast(a1));
    unsigned long long s = fma2(u, tp, u);          // silu(h) = (h/2)(1+tanh(h/2))
    acc = fma2(s, w2p, acc);
}

// ---- prologue 1: tiled x transpose (coalesced both sides) ----
__global__ void prep_x_t(const float* __restrict__ x) {
    __shared__ float tile[32][33];
    int bx = blockIdx.x;             // 64 b-tiles of 32
    int by = blockIdx.y;             // 2 i-tiles of 32
    int tx = threadIdx.x, ty = threadIdx.y;   // 32 x 8
#pragma unroll
    for (int k = 0; k < 4; k++) {
        int b = bx * 32 + ty + k * 8;
        tile[ty + k * 8][tx] = x[b * DIN + by * 32 + tx];
    }
    __syncthreads();
#pragma unroll
    for (int k = 0; k < 4; k++) {
        int i = by * 32 + ty + k * 8;
        g_xT[i * BB + bx * 32 + tx] = tile[tx][ty + k * 8];
    }
}

// ---- prologue 2: weight repack + B2 row-sum ----
#define NRP (DOUT * DIN * HP)
__global__ void prep_w(const float* __restrict__ W1, const float* __restrict__ W2,
                       const float* __restrict__ B1, const float* __restrict__ B2) {
    int t = blockIdx.x * 256 + threadIdx.x;
    if (t < NRP) {
        int hp = t & 15;
        int i  = (t >> 4) & 63;
        int o  = t >> 10;
        int h0 = hp * 2, h1 = h0 + 1;

        const float* w1b = W1 + (((size_t)i * DOUT + o) * HH) * 7;  // W1[i][o][h][f]
        float* dst = ((float*)g_w1p) + (size_t)t * 16;
#pragma unroll
        for (int f = 0; f < 7; f++) {
            dst[2 * f]     = 0.5f * w1b[h0 * 7 + f];
            dst[2 * f + 1] = 0.5f * w1b[h1 * 7 + f];
        }
        const float* b1b = B1 + ((size_t)i * DOUT + o) * HH;
        dst[14] = 0.5f * b1b[h0];
        dst[15] = 0.5f * b1b[h1];

        const float* w2b = W2 + ((size_t)i * DOUT + o) * HH;  // W2[i][o][0][h]
        float* d2 = ((float*)g_w2) + (((size_t)o * DIN + i) * HP + hp) * 2;
        d2[0] = w2b[h0];
        d2[1] = w2b[h1];
        return;
    }
    t -= NRP;
    if (t < DOUT) {
        float s = 0.f;
        for (int i = 0; i < DIN; i++) s += B2[i * DOUT + t];
        g_sumB2[t] = s;
    }
}

// ---- prologue 3: initialize out with bias row-sums (atomic accumulation base) ----
__global__ void out_init(float* __restrict__ out) {
    int t = blockIdx.x * 256 + threadIdx.x;      // t = b*DOUT + o
    if (t < BB * DOUT) out[t] = g_sumB2[t & 63];
}

// ---- main fused kernel (launch #4 -> profiled) ----
// CTA = 4 warps (128 thr), one (o, iq, bo): 4 i's, 512 b's. 4.5KB slice in smem.
// Lane owns 4 b's. __launch_bounds__(128,6): reg cap 85 -> 6 CTAs/SM = 24 warps
// (RF is the residency limiter: 65536 regs/SM / (regs*128)).
// grid = 64 o * 16 iq * 4 bo = 4096 CTAs.
__global__ void __launch_bounds__(128, 6) kan_main(float* __restrict__ out) {
    __shared__ __align__(16) ulonglong2 s_w1[IPQ * HP * 4];   // 256 entries, 4 KB
    __shared__ __align__(16) ulonglong2 s_w2[IPQ * HP / 2];   // 32 entries, 0.5 KB

    int lane = threadIdx.x & 31;
    int w    = threadIdx.x >> 5;
    int o    = blockIdx.x & 63;
    int iq   = (blockIdx.x >> 6) & 15;
    int bo   = blockIdx.x >> 10;            // 0..3
    int b0   = bo * 512 + w * 128 + lane;
    int i0   = iq * IPQ;

    // cooperative weight-slice load (coalesced LDG.128 -> STS.128)
    {
        const ulonglong2* gw1 = ((const ulonglong2*)g_w1p) + ((size_t)o * DIN + i0) * (HP * 4);
        const ulonglong2* gw2 = ((const ulonglong2*)g_w2)  + ((size_t)o * DIN + i0) * (HP / 2);
#pragma unroll
        for (int t = threadIdx.x; t < IPQ * HP * 4; t += 128) s_w1[t] = gw1[t];
        if (threadIdx.x < IPQ * HP / 2) s_w2[threadIdx.x] = gw2[threadIdx.x];
    }
    __syncthreads();

    unsigned long long accA = 0ull, accB = 0ull, accC = 0ull, accD = 0ull;
    unsigned long long fA[7], fB[7], fC[7], fD[7];

    const float* xr = g_xT + i0 * BB + b0;

#pragma unroll 1
    for (int ii = 0; ii < IPQ; ii++) {
        const float* xn = xr + ii * BB;
        make_feats(xn[0],  fA);
        make_feats(xn[32], fB);
        make_feats(xn[64], fC);
        make_feats(xn[96], fD);

        const ulonglong2* wr  = s_w1 + ii * (HP * 4);
        const ulonglong2* w2r = s_w2 + ii * (HP / 2);

#pragma unroll 2
        for (int hpp = 0; hpp < HP / 2; hpp++) {
            ulonglong2 w2q = w2r[hpp];      // W2 pairs for hp=2hpp (.x), 2hpp+1 (.y)
#pragma unroll
            for (int k = 0; k < 2; k++) {
                int hp = 2 * hpp + k;
                ulonglong2 q0 = wr[hp * 4 + 0];
                ulonglong2 q1 = wr[hp * 4 + 1];
                ulonglong2 q2 = wr[hp * 4 + 2];
                ulonglong2 q3 = wr[hp * 4 + 3];
                unsigned long long w2p = k ? w2q.y : w2q.x;
                edge_eval(q0, q1, q2, q3, w2p, fA, accA);
                edge_eval(q0, q1, q2, q3, w2p, fB, accB);
                edge_eval(q0, q1, q2, q3, w2p, fC, accC);
                edge_eval(q0, q1, q2, q3, w2p, fD, accD);
            }
        }
    }

    float r0, r1;
    unpack2(accA, r0, r1); atomicAdd(&out[(size_t)(b0      ) * DOUT + o], r0 + r1);
    unpack2(accB, r0, r1); atomicAdd(&out[(size_t)(b0 + 32 ) * DOUT + o], r0 + r1);
    unpack2(accC, r0, r1); atomicAdd(&out[(size_t)(b0 + 64 ) * DOUT + o], r0 + r1);
    unpack2(accD, r0, r1); atomicAdd(&out[(size_t)(b0 + 96 ) * DOUT + o], r0 + r1);
}

extern "C" void kernel_launch(void* const* d_in, const int* in_sizes, int n_in,
                              void* d_out, int out_size) {
    const float* x  = (const float*)d_in[0];
    const float* W1 = (const float*)d_in[1];
    const float* W2 = (const float*)d_in[2];
    const float* B1 = (const float*)d_in[3];
    const float* B2 = (const float*)d_in[4];
    (void)in_sizes; (void)n_in; (void)out_size;

    dim3 tb(32, 8);
    dim3 tg(64, 2);
    prep_x_t<<<tg, tb>>>(x);                                    // launch 1
    prep_w<<<(NRP + DOUT + 255) / 256, 256>>>(W1, W2, B1, B2);  // launch 2
    out_init<<<(BB * DOUT + 255) / 256, 256>>>((float*)d_out);  // launch 3
    kan_main<<<4096, 128>>>((float*)d_out);                     // launch 4 (profiled)
}

// round 16
// speedup vs baseline: 1.1442x; 1.0006x over previous
#include <cuda_runtime.h>

#define DIN  64
#define DOUT 64
#define HH   32
#define HP   16          // h-pairs
#define BB   2048
#define IQ   16          // Din split factor
#define IPQ  (DIN / IQ)  // 4 i's per CTA

// ---- device scratch ----
// w1p record per (o,i,hp): 64B = {0.5*w_f(h0),0.5*w_f(h1) f=0..6, 0.5*B1(h0),0.5*B1(h1)}
__device__ __align__(16) unsigned long long g_w1p[DOUT * DIN * HP * 8];   // 4 MB
// w2: per (o,i): 16 hp-pairs of W2 = 128B
__device__ __align__(16) unsigned long long g_w2[DOUT * DIN * HP];        // 1 MB
__device__ float g_xT[DIN * BB];
__device__ float g_sumB2[DOUT];

// ---- f32x2 helpers ----
__device__ __forceinline__ unsigned long long pack2(float a, float b) {
    unsigned long long v;
    asm("mov.b64 %0, {%1, %2};" : "=l"(v) : "f"(a), "f"(b));
    return v;
}
__device__ __forceinline__ void unpack2(unsigned long long v, float& a, float& b) {
    asm("mov.b64 {%0, %1}, %2;" : "=f"(a), "=f"(b) : "l"(v));
}
__device__ __forceinline__ unsigned long long fma2(unsigned long long a,
                                                   unsigned long long b,
                                                   unsigned long long c) {
    unsigned long long d;
    asm("fma.rn.f32x2 %0, %1, %2, %3;" : "=l"(d) : "l"(a), "l"(b), "l"(c));
    return d;
}
__device__ __forceinline__ float tanh_fast(float x) {
    float y;
    asm("tanh.approx.f32 %0, %1;" : "=f"(y) : "f"(x));
    return y;
}

// feats order matches reference: [x, sin(1x), sin(2x), sin(4x), cos(1x), cos(2x), cos(4x)]
// 2x/4x via double-angle on the FMA pipe: MUFU only for sin(x), cos(x) (+tanh later).
__device__ __forceinline__ void make_feats(float x, unsigned long long* fp) {
    float s1 = __sinf(x), c1 = __cosf(x);
    float t1 = s1 + s1;
    float s2 = t1 * c1;
    float c2 = fmaf(-t1, s1, 1.f);
    float t2 = s2 + s2;
    float s4 = t2 * c2;
    float c4 = fmaf(-t2, s2, 1.f);
    fp[0] = pack2(x,  x);
    fp[1] = pack2(s1, s1);
    fp[2] = pack2(s2, s2);
    fp[3] = pack2(s4, s4);
    fp[4] = pack2(c1, c1);
    fp[5] = pack2(c2, c2);
    fp[6] = pack2(c4, c4);
}

// one edge-MLP evaluation for one b (h-pair packed), weights pre-scaled by 0.5
__device__ __forceinline__ void edge_eval(ulonglong2 q0, ulonglong2 q1,
                                          ulonglong2 q2, ulonglong2 q3,
                                          unsigned long long w2p,
                                          const unsigned long long* f,
                                          unsigned long long& acc) {
    unsigned long long u = fma2(q0.x, f[0], q3.y);  // q3.y = 0.5*B1 pair
    u = fma2(q0.y, f[1], u);
    u = fma2(q1.x, f[2], u);
    u = fma2(q1.y, f[3], u);
    u = fma2(q2.x, f[4], u);
    u = fma2(q2.y, f[5], u);
    u = fma2(q3.x, f[6], u);                        // u = h/2
    float a0, a1;
    unpack2(u, a0, a1);
    unsigned long long tp = pack2(tanh_fast(a0), tanh_fast(a1));
    unsigned long long s = fma2(u, tp, u);          // silu(h) = (h/2)(1+tanh(h/2))
    acc = fma2(s, w2p, acc);
}

// ---- prologue 1: tiled x transpose (coalesced both sides) ----
__global__ void prep_x_t(const float* __restrict__ x) {
    __shared__ float tile[32][33];
    int bx = blockIdx.x;             // 64 b-tiles of 32
    int by = blockIdx.y;             // 2 i-tiles of 32
    int tx = threadIdx.x, ty = threadIdx.y;   // 32 x 8
#pragma unroll
    for (int k = 0; k < 4; k++) {
        int b = bx * 32 + ty + k * 8;
        tile[ty + k * 8][tx] = x[b * DIN + by * 32 + tx];
    }
    __syncthreads();
#pragma unroll
    for (int k = 0; k < 4; k++) {
        int i = by * 32 + ty + k * 8;
        g_xT[i * BB + bx * 32 + tx] = tile[tx][ty + k * 8];
    }
}

// ---- prologue 2: weight repack + B2 row-sum ----
#define NRP (DOUT * DIN * HP)
__global__ void prep_w(const float* __restrict__ W1, const float* __restrict__ W2,
                       const float* __restrict__ B1, const float* __restrict__ B2) {
    int t = blockIdx.x * 256 + threadIdx.x;
    if (t < NRP) {
        int hp = t & 15;
        int i  = (t >> 4) & 63;
        int o  = t >> 10;
        int h0 = hp * 2, h1 = h0 + 1;

        const float* w1b = W1 + (((size_t)i * DOUT + o) * HH) * 7;  // W1[i][o][h][f]
        float* dst = ((float*)g_w1p) + (size_t)t * 16;
#pragma unroll
        for (int f = 0; f < 7; f++) {
            dst[2 * f]     = 0.5f * w1b[h0 * 7 + f];
            dst[2 * f + 1] = 0.5f * w1b[h1 * 7 + f];
        }
        const float* b1b = B1 + ((size_t)i * DOUT + o) * HH;
        dst[14] = 0.5f * b1b[h0];
        dst[15] = 0.5f * b1b[h1];

        const float* w2b = W2 + ((size_t)i * DOUT + o) * HH;  // W2[i][o][0][h]
        float* d2 = ((float*)g_w2) + (((size_t)o * DIN + i) * HP + hp) * 2;
        d2[0] = w2b[h0];
        d2[1] = w2b[h1];
        return;
    }
    t -= NRP;
    if (t < DOUT) {
        float s = 0.f;
        for (int i = 0; i < DIN; i++) s += B2[i * DOUT + t];
        g_sumB2[t] = s;
    }
}

// ---- prologue 3: initialize out with bias row-sums (atomic accumulation base) ----
__global__ void out_init(float* __restrict__ out) {
    int t = blockIdx.x * 256 + threadIdx.x;      // t = b*DOUT + o
    if (t < BB * DOUT) out[t] = g_sumB2[t & 63];
}

// ---- main fused kernel (launch #4 -> profiled) ----
// CTA = 4 warps (128 thr), one (o, iq, bo): 4 i's, 512 b's. 4.5KB slice in smem.
// Lane owns 4 b's. hpp unroll 1 frees in-flight operand regs;
// __launch_bounds__(128,7): reg cap 73 -> 7 CTAs/SM = 28 warps (+17% vs R15).
// grid = 64 o * 16 iq * 4 bo = 4096 CTAs.
__global__ void __launch_bounds__(128, 7) kan_main(float* __restrict__ out) {
    __shared__ __align__(16) ulonglong2 s_w1[IPQ * HP * 4];   // 256 entries, 4 KB
    __shared__ __align__(16) ulonglong2 s_w2[IPQ * HP / 2];   // 32 entries, 0.5 KB

    int lane = threadIdx.x & 31;
    int w    = threadIdx.x >> 5;
    int o    = blockIdx.x & 63;
    int iq   = (blockIdx.x >> 6) & 15;
    int bo   = blockIdx.x >> 10;            // 0..3
    int b0   = bo * 512 + w * 128 + lane;
    int i0   = iq * IPQ;

    // cooperative weight-slice load (coalesced LDG.128 -> STS.128)
    {
        const ulonglong2* gw1 = ((const ulonglong2*)g_w1p) + ((size_t)o * DIN + i0) * (HP * 4);
        const ulonglong2* gw2 = ((const ulonglong2*)g_w2)  + ((size_t)o * DIN + i0) * (HP / 2);
#pragma unroll
        for (int t = threadIdx.x; t < IPQ * HP * 4; t += 128) s_w1[t] = gw1[t];
        if (threadIdx.x < IPQ * HP / 2) s_w2[threadIdx.x] = gw2[threadIdx.x];
    }
    __syncthreads();

    unsigned long long accA = 0ull, accB = 0ull, accC = 0ull, accD = 0ull;
    unsigned long long fA[7], fB[7], fC[7], fD[7];

    const float* xr = g_xT + i0 * BB + b0;

#pragma unroll 1
    for (int ii = 0; ii < IPQ; ii++) {
        const float* xn = xr + ii * BB;
        make_feats(xn[0],  fA);
        make_feats(xn[32], fB);
        make_feats(xn[64], fC);
        make_feats(xn[96], fD);

        const ulonglong2* wr  = s_w1 + ii * (HP * 4);
        const ulonglong2* w2r = s_w2 + ii * (HP / 2);

#pragma unroll 1
        for (int hpp = 0; hpp < HP / 2; hpp++) {
            ulonglong2 w2q = w2r[hpp];      // W2 pairs for hp=2hpp (.x), 2hpp+1 (.y)
#pragma unroll
            for (int k = 0; k < 2; k++) {
                int hp = 2 * hpp + k;
                ulonglong2 q0 = wr[hp * 4 + 0];
                ulonglong2 q1 = wr[hp * 4 + 1];
                ulonglong2 q2 = wr[hp * 4 + 2];
                ulonglong2 q3 = wr[hp * 4 + 3];
                unsigned long long w2p = k ? w2q.y : w2q.x;
                edge_eval(q0, q1, q2, q3, w2p, fA, accA);
                edge_eval(q0, q1, q2, q3, w2p, fB, accB);
                edge_eval(q0, q1, q2, q3, w2p, fC, accC);
                edge_eval(q0, q1, q2, q3, w2p, fD, accD);
            }
        }
    }

    float r0, r1;
    unpack2(accA, r0, r1); atomicAdd(&out[(size_t)(b0      ) * DOUT + o], r0 + r1);
    unpack2(accB, r0, r1); atomicAdd(&out[(size_t)(b0 + 32 ) * DOUT + o], r0 + r1);
    unpack2(accC, r0, r1); atomicAdd(&out[(size_t)(b0 + 64 ) * DOUT + o], r0 + r1);
    unpack2(accD, r0, r1); atomicAdd(&out[(size_t)(b0 + 96 ) * DOUT + o], r0 + r1);
}

extern "C" void kernel_launch(void* const* d_in, const int* in_sizes, int n_in,
                              void* d_out, int out_size) {
    const float* x  = (const float*)d_in[0];
    const float* W1 = (const float*)d_in[1];
    const float* W2 = (const float*)d_in[2];
    const float* B1 = (const float*)d_in[3];
    const float* B2 = (const float*)d_in[4];
    (void)in_sizes; (void)n_in; (void)out_size;

    dim3 tb(32, 8);
    dim3 tg(64, 2);
    prep_x_t<<<tg, tb>>>(x);                                    // launch 1
    prep_w<<<(NRP + DOUT + 255) / 256, 256>>>(W1, W2, B1, B2);  // launch 2
    out_init<<<(BB * DOUT + 255) / 256, 256>>>((float*)d_out);  // launch 3
    kan_main<<<4096, 128>>>((float*)d_out);                     // launch 4 (profiled)
}